// round 12
// baseline (speedup 1.0000x reference)
#include <cuda_runtime.h>
#include <cuda_bf16.h>

// Scratch for pooled diff: [32, 128, 128] floats = 2 MB (static, no allocs).
__device__ float g_diff[32 * 128 * 128];

// Finish counter: monotonic, +NBLK per launch -> graph-replay-safe, no reset.
__device__ unsigned long long g_done = 0;

#define NBLK   4096        // K1 blocks (128 py x 32 b)
#define NSLICE 512         // last-finisher blocks that run the epilogue
#define NSEG   131072      // 4-wide TV segments (32*128*32)
#define SEG_PER_SLICE (NSEG / NSLICE)   // 256

__global__ __launch_bounds__(128) void fused_spa_kernel(
    const float* __restrict__ org, const float* __restrict__ enh,
    float* __restrict__ out)
{
    const int t  = threadIdx.x;   // pooled col 0..127
    const int py = blockIdx.x;    // pooled row 0..127
    const int b  = blockIdx.y;    // batch 0..31

    if (py == 0 && b == 0 && t == 0) out[0] = 0.f;

    // ---- Phase 1: pooled channel-mean diff (proven HBM-ceiling config) ----
    float s = 0.f;
#pragma unroll
    for (int c = 0; c < 3; ++c) {
#pragma unroll
        for (int dy = 0; dy < 4; ++dy) {
            const size_t off = (((size_t)(b * 3 + c) * 512) + (size_t)(py * 4 + dy)) * 512
                               + (size_t)(4 * t);
            const float4 o = *reinterpret_cast<const float4*>(org + off);
            const float4 e = *reinterpret_cast<const float4*>(enh + off);
            s += (o.x - e.x) + (o.y - e.y) + (o.z - e.z) + (o.w - e.w);
        }
    }
    g_diff[((b << 7) + py) * 128 + t] = s * (1.0f / 48.0f);   // /(3ch*16px)

    // ---- Finish-order ticket ----
    __syncthreads();               // whole block's g_diff row issued
    __shared__ unsigned long long sh_tk;
    if (t == 0) {
        __threadfence();           // publish this block's g_diff (and out=0)
        sh_tk = atomicAdd(&g_done, 1ULL);
    }
    __syncthreads();
    const unsigned long long tk_raw = sh_tk;
    const int tk = (int)(tk_raw & (NBLK - 1));   // in-launch ticket 0..4095

    if (tk < NBLK - NSLICE) return;              // early finishers exit

    // ---- Last 512 finishers: wait for all 4096 arrivals, then epilogue ----
    if (t == 0) {
        const unsigned long long target = (tk_raw | (NBLK - 1)) + 1ULL;
        volatile unsigned long long* vd = &g_done;
        while (*vd < target) { }
        __threadfence();           // acquire: all blocks' g_diff visible
    }
    __syncthreads();

    const int slice = tk - (NBLK - NSLICE);      // 0..511
    float v = 0.f;

#pragma unroll
    for (int it = 0; it < SEG_PER_SLICE / 128; ++it) {   // 2 segments/thread
        const int seg = slice * SEG_PER_SLICE + it * 128 + t;
        const int bb  = seg >> 12;        // 4096 segments per image
        const int r   = seg & 4095;
        const int y   = r >> 5;           // row 0..127
        const int sx  = (r & 31) << 2;    // segment start col

        const float* __restrict__ img = g_diff + ((size_t)bb << 14);
        const int p = (y << 7) + sx;

        const float4 c  = *reinterpret_cast<const float4*>(img + p);
        const float  l  = (sx > 0)   ? img[p - 1] : 0.f;
        const float  rr = (sx < 124) ? img[p + 4] : 0.f;

        float4 u, dn;
        if (y > 0)   u  = *reinterpret_cast<const float4*>(img + p - 128);
        else         u  = make_float4(0.f, 0.f, 0.f, 0.f);
        if (y < 127) dn = *reinterpret_cast<const float4*>(img + p + 128);
        else         dn = make_float4(0.f, 0.f, 0.f, 0.f);

        float a;
        a = c.x - l;    v += a * a;
        a = c.x - c.y;  v += a * a;
        a = c.x - u.x;  v += a * a;
        a = c.x - dn.x; v += a * a;

        a = c.y - c.x;  v += a * a;
        a = c.y - c.z;  v += a * a;
        a = c.y - u.y;  v += a * a;
        a = c.y - dn.y; v += a * a;

        a = c.z - c.y;  v += a * a;
        a = c.z - c.w;  v += a * a;
        a = c.z - u.z;  v += a * a;
        a = c.z - dn.z; v += a * a;

        a = c.w - c.z;  v += a * a;
        a = c.w - rr;   v += a * a;
        a = c.w - u.w;  v += a * a;
        a = c.w - dn.w; v += a * a;
    }

    // warp reduce
#pragma unroll
    for (int o = 16; o > 0; o >>= 1)
        v += __shfl_xor_sync(0xFFFFFFFFu, v, o);

    __shared__ float ws[4];
    if ((t & 31) == 0) ws[t >> 5] = v;
    __syncthreads();

    if (t == 0) {
        const float vv = ws[0] + ws[1] + ws[2] + ws[3];
        atomicAdd(out, vv * (1.0f / (32.0f * 128.0f * 128.0f)));
    }
}

extern "C" void kernel_launch(void* const* d_in, const int* in_sizes, int n_in,
                              void* d_out, int out_size)
{
    const float* org = (const float*)d_in[0];
    const float* enh = (const float*)d_in[1];
    float* out = (float*)d_out;

    dim3 g1(128, 32);
    fused_spa_kernel<<<g1, 128>>>(org, enh, out);
}

// round 13
// speedup vs baseline: 1.0995x; 1.0995x over previous
#include <cuda_runtime.h>
#include <cuda_bf16.h>

// Scratch for pooled diff: [32, 128, 128] floats = 2 MB (static, no allocs).
__device__ float g_diff[32 * 128 * 128];

// K1: pooled diff. grid = (128 pooled rows, 32 batch), block = 128 threads
// (one thread per pooled column). Per channel, ALL 8 float4 loads (4 org +
// 4 enh rows) are issued before any arithmetic -> 8 independent LDG.128 in
// flight per thread (ptxas was previously budget-limited at regs=32 / ~5
// in flight). __launch_bounds__(128, 8) lifts the ceiling to 64 regs.
__global__ __launch_bounds__(128, 8) void pool_diff_kernel(
    const float* __restrict__ org, const float* __restrict__ enh,
    float* __restrict__ out)
{
    // Allow the dependent kernel (K2) to begin launching early (PDL).
    asm volatile("griddepcontrol.launch_dependents;" ::: "memory");

    const int t  = threadIdx.x;   // pooled col 0..127
    const int py = blockIdx.x;    // pooled row 0..127
    const int b  = blockIdx.y;    // batch 0..31

    if (py == 0 && b == 0 && t == 0) out[0] = 0.f;

    float s = 0.f;
#pragma unroll
    for (int c = 0; c < 3; ++c) {
        const size_t base = (((size_t)(b * 3 + c) * 512) + (size_t)(py * 4)) * 512
                            + (size_t)(4 * t);
        float4 o0, o1, o2, o3, e0, e1, e2, e3;
        o0 = *reinterpret_cast<const float4*>(org + base);
        o1 = *reinterpret_cast<const float4*>(org + base + 512);
        o2 = *reinterpret_cast<const float4*>(org + base + 1024);
        o3 = *reinterpret_cast<const float4*>(org + base + 1536);
        e0 = *reinterpret_cast<const float4*>(enh + base);
        e1 = *reinterpret_cast<const float4*>(enh + base + 512);
        e2 = *reinterpret_cast<const float4*>(enh + base + 1024);
        e3 = *reinterpret_cast<const float4*>(enh + base + 1536);

        s += (o0.x - e0.x) + (o0.y - e0.y) + (o0.z - e0.z) + (o0.w - e0.w);
        s += (o1.x - e1.x) + (o1.y - e1.y) + (o1.z - e1.z) + (o1.w - e1.w);
        s += (o2.x - e2.x) + (o2.y - e2.y) + (o2.z - e2.z) + (o2.w - e2.w);
        s += (o3.x - e3.x) + (o3.y - e3.y) + (o3.z - e3.z) + (o3.w - e3.w);
    }
    // mean over 3 channels and 16 pixels = /48
    g_diff[((b << 7) + py) * 128 + t] = s * (1.0f / 48.0f);
}

// K2: 4-direction shift-diff^2 + full reduction, vectorized (1 thread = one
// 4-wide row segment). 512 blocks x 256 threads = 131072 threads (R8 config,
// best measured under PDL: small blocks slot into SMs as K1's tail drains).
__global__ __launch_bounds__(256) void tv_reduce_kernel(float* __restrict__ out)
{
    const int idx = blockIdx.x * 256 + threadIdx.x;   // 0 .. 131071
    const int b   = idx >> 12;        // 4096 segments per image
    const int r   = idx & 4095;
    const int y   = r >> 5;           // row 0..127
    const int sx  = (r & 31) << 2;    // segment start col: 0,4,...,124

    const float* __restrict__ img = g_diff + ((size_t)b << 14);
    const int p = (y << 7) + sx;

    // Wait for K1's memory to be visible before reading g_diff / out.
    asm volatile("griddepcontrol.wait;" ::: "memory");

    const float4 c  = *reinterpret_cast<const float4*>(img + p);
    const float  l  = (sx > 0)   ? img[p - 1] : 0.f;
    const float  rr = (sx < 124) ? img[p + 4] : 0.f;

    float4 u, dn;
    if (y > 0)   u  = *reinterpret_cast<const float4*>(img + p - 128);
    else         u  = make_float4(0.f, 0.f, 0.f, 0.f);
    if (y < 127) dn = *reinterpret_cast<const float4*>(img + p + 128);
    else         dn = make_float4(0.f, 0.f, 0.f, 0.f);

    float v;
    {
        float a;
        a = c.x - l;    v  = a * a;
        a = c.x - c.y;  v += a * a;
        a = c.x - u.x;  v += a * a;
        a = c.x - dn.x; v += a * a;

        a = c.y - c.x;  v += a * a;
        a = c.y - c.z;  v += a * a;
        a = c.y - u.y;  v += a * a;
        a = c.y - dn.y; v += a * a;

        a = c.z - c.y;  v += a * a;
        a = c.z - c.w;  v += a * a;
        a = c.z - u.z;  v += a * a;
        a = c.z - dn.z; v += a * a;

        a = c.w - c.z;  v += a * a;
        a = c.w - rr;   v += a * a;
        a = c.w - u.w;  v += a * a;
        a = c.w - dn.w; v += a * a;
    }

    // warp reduce
#pragma unroll
    for (int o = 16; o > 0; o >>= 1)
        v += __shfl_xor_sync(0xFFFFFFFFu, v, o);

    __shared__ float ws[8];
    if ((threadIdx.x & 31) == 0) ws[threadIdx.x >> 5] = v;
    __syncthreads();

    if (threadIdx.x < 32) {
        float vv = (threadIdx.x < 8) ? ws[threadIdx.x] : 0.f;
#pragma unroll
        for (int o = 4; o > 0; o >>= 1)
            vv += __shfl_xor_sync(0xFFFFFFFFu, vv, o);
        if (threadIdx.x == 0)
            atomicAdd(out, vv * (1.0f / (32.0f * 128.0f * 128.0f)));
    }
}

extern "C" void kernel_launch(void* const* d_in, const int* in_sizes, int n_in,
                              void* d_out, int out_size)
{
    const float* org = (const float*)d_in[0];
    const float* enh = (const float*)d_in[1];
    float* out = (float*)d_out;

    dim3 g1(128, 32);
    pool_diff_kernel<<<g1, 128>>>(org, enh, out);

    // K2 with programmatic dependent launch: spins up during K1, waits for
    // K1's completion inside the kernel (griddepcontrol.wait).
    cudaLaunchConfig_t cfg = {};
    cfg.gridDim  = dim3(512, 1, 1);
    cfg.blockDim = dim3(256, 1, 1);
    cfg.dynamicSmemBytes = 0;
    cfg.stream = 0;

    cudaLaunchAttribute attr[1];
    attr[0].id = cudaLaunchAttributeProgrammaticStreamSerialization;
    attr[0].val.programmaticStreamSerializationAllowed = 1;
    cfg.attrs = attr;
    cfg.numAttrs = 1;

    cudaLaunchKernelEx(&cfg, tv_reduce_kernel, out);
}